// round 12
// baseline (speedup 1.0000x reference)
#include <cuda_runtime.h>
#include <cuda_fp16.h>

// Problem constants (fixed shapes)
#define N_MAX 50000
#define M_MAX 800000
#define D 96          // K*FAC
#define KCAP 8
#define FAC 12

#define CAP 14                        // cached neighbors per node in smem (fp16)
#define WSLAB (CAP * 768)             // per-warp slab: 10752 B
#define ROUTE_SMEM (4 * WSLAB)        // 43008 B per 128-thread block -> 5 blocks/SM
#define ROUTE_GRID 740                // 148 SMs x 5 resident blocks: one wave

typedef unsigned long long u64;

// Static scratch (no allocations allowed)
__device__ __half g_zh_a[N_MAX * D];   // fp16 z double-buffer A (gather source)
__device__ __half g_zh_b[N_MAX * D];   // fp16 z double-buffer B
__device__ float  g_z32_a[N_MAX * D];  // fp32 z double-buffer A (self-term)
__device__ float  g_z32_b[N_MAX * D];  // fp32 z double-buffer B
__device__ float  g_wt[D * 256];       // W transposed to [out=96][in=256]
__device__ int    g_deg[N_MAX];
__device__ int    g_rowptr[N_MAX + 1];
__device__ int    g_cursor[N_MAX];
__device__ int    g_colsrc[M_MAX];
__device__ int    g_bsum[64];
__device__ int    g_boff[64];
__device__ int    g_dhist[64];
__device__ int    g_dcur[64];
__device__ int    g_perm[N_MAX];
__device__ int    g_work[4];           // per-layer work-stealing counters

// ---------------- packed f32x2 helpers (init GEMM only) --------------------
__device__ __forceinline__ u64 pk2(float lo, float hi) {
    u64 r; asm("mov.b64 %0,{%1,%2};" : "=l"(r) : "f"(lo), "f"(hi)); return r;
}
__device__ __forceinline__ float2 upk2(u64 v) {
    float2 f; asm("mov.b64 {%0,%1},%2;" : "=f"(f.x), "=f"(f.y) : "l"(v)); return f;
}
__device__ __forceinline__ u64 fma2_(u64 a, u64 b, u64 c) {
    u64 d; asm("fma.rn.f32x2 %0,%1,%2,%3;" : "=l"(d) : "l"(a), "l"(b), "l"(c)); return d;
}

// 8-lane group sum (3-shuffle butterfly; fp32 redux unsupported on sm_103)
__device__ __forceinline__ float gsum8(float v, unsigned mask) {
    v += __shfl_xor_sync(mask, v, 1);
    v += __shfl_xor_sync(mask, v, 2);
    v += __shfl_xor_sync(mask, v, 4);
    return v;
}

// ---------------------------------------------------------------------------
// zero + W transpose fused; also resets work-stealing counters each replay.
__global__ void zero_wt_kernel(const float* __restrict__ W, int n) {
    int i = blockIdx.x * blockDim.x + threadIdx.x;
    if (i < n) g_deg[i] = 0;
    if (i < 64) g_dhist[i] = 0;
    if (i < 4) g_work[i] = 0;
    if (i < D * 256) {
        int o = i >> 8, c = i & 255;
        int k = o / FAC, oo = o % FAC;
        g_wt[i] = W[k * (256 * FAC) + c * FAC + oo];
    }
}

// ---------------------------------------------------------------------------
// Init layer fused with prep: Z = relu(X.Wt + b) staged in smem, then
// z = l2norm(Z) written to z32_a (fp32) + zh_a (fp16). f32x2 FMA mainloop.
__global__ void __launch_bounds__(96) init_gemm(const float* __restrict__ X,
                                                const float* __restrict__ bv, int n) {
    __shared__ float xs[32][256];
    __shared__ float os[32][96];
    int t = threadIdx.x;
    int nb = blockIdx.x * 32;
    for (int j = t; j < 32 * 256; j += 96) {
        int q = j >> 8;
        xs[q][j & 255] = (nb + q < n) ? X[nb * 256 + j] : 0.f;
    }
    __syncthreads();

    u64 acc[32];
#pragma unroll
    for (int q = 0; q < 32; q++) acc[q] = 0ull;

    const float4* wrow = (const float4*)(g_wt + t * 256);
#pragma unroll 2
    for (int i4 = 0; i4 < 64; i4++) {
        float4 w = wrow[i4];
        u64 w01 = pk2(w.x, w.y);
        u64 w23 = pk2(w.z, w.w);
#pragma unroll
        for (int q = 0; q < 32; q++) {
            float4 xv = *(const float4*)&xs[q][i4 * 4];
            acc[q] = fma2_(w01, pk2(xv.x, xv.y), acc[q]);
            acc[q] = fma2_(w23, pk2(xv.z, xv.w), acc[q]);
        }
    }
    float bb = bv[t];
#pragma unroll
    for (int q = 0; q < 32; q++) {
        float2 h = upk2(acc[q]);
        os[q][t] = fmaxf(h.x + h.y + bb, 0.f);   // relu(Z)
    }
    __syncthreads();

    // prep: per (node, capsule) l2norm -> z32_a + zh_a
    for (int idx = t; idx < 32 * KCAP; idx += 96) {
        int q = idx >> 3, cp = idx & 7;
        if (nb + q >= n) continue;
        const float* r = &os[q][cp * FAC];
        float v[12];
        float s = 0.f;
#pragma unroll
        for (int i = 0; i < 12; i++) { v[i] = r[i]; s += v[i] * v[i]; }
        float rn = rsqrtf(s + 1e-12f);
#pragma unroll
        for (int i = 0; i < 12; i++) v[i] *= rn;
        int gi = ((nb + q) * KCAP + cp) * FAC;
        float4* zp = (float4*)(g_z32_a + gi);
        zp[0] = make_float4(v[0], v[1], v[2], v[3]);
        zp[1] = make_float4(v[4], v[5], v[6], v[7]);
        zp[2] = make_float4(v[8], v[9], v[10], v[11]);
        uint2* zh = (uint2*)(g_zh_a + gi);
        __half2 h0 = __floats2half2_rn(v[0], v[1]);
        __half2 h1 = __floats2half2_rn(v[2], v[3]);
        __half2 h2 = __floats2half2_rn(v[4], v[5]);
        __half2 h3 = __floats2half2_rn(v[6], v[7]);
        __half2 h4 = __floats2half2_rn(v[8], v[9]);
        __half2 h5 = __floats2half2_rn(v[10], v[11]);
        zh[0] = make_uint2(*(unsigned*)&h0, *(unsigned*)&h1);
        zh[1] = make_uint2(*(unsigned*)&h2, *(unsigned*)&h3);
        zh[2] = make_uint2(*(unsigned*)&h4, *(unsigned*)&h5);
    }
}

// ---------------------------------------------------------------------------
// CSR build: hist -> 3-phase hierarchical scan (with perm stages fused)
__global__ void hist_kernel(const int* __restrict__ edges, int m) {
    int e = blockIdx.x * blockDim.x + threadIdx.x;
    if (e < m) atomicAdd(&g_deg[edges[m + e]], 1);
}

// phase 1: block-local exclusive scan of degrees + degree histogram (fused)
__global__ void scan1_kernel(int n) {
    __shared__ int wsum[32];
    __shared__ int h[64];
    int t = threadIdx.x, lane = t & 31, wid = t >> 5;
    if (t < 64) h[t] = 0;
    int idx = blockIdx.x * 1024 + t;
    int v = (idx < n) ? g_deg[idx] : 0;
    int x = v;
#pragma unroll
    for (int off = 1; off < 32; off <<= 1) {
        int y = __shfl_up_sync(0xffffffffu, x, off);
        if (lane >= off) x += y;
    }
    if (lane == 31) wsum[wid] = x;
    __syncthreads();
    if (wid == 0) {
        int w = wsum[lane];
#pragma unroll
        for (int off = 1; off < 32; off <<= 1) {
            int y = __shfl_up_sync(0xffffffffu, w, off);
            if (lane >= off) w += y;
        }
        wsum[lane] = w;
    }
    if (idx < n) atomicAdd(&h[min(v, 63)], 1);
    __syncthreads();
    int pre = (wid > 0) ? wsum[wid - 1] : 0;
    if (idx < n) g_rowptr[idx] = pre + x - v;   // block-local exclusive
    if (t == 1023) g_bsum[blockIdx.x] = pre + x;
    if (t < 64 && h[t]) atomicAdd(&g_dhist[t], h[t]);
}

// phase 2: scan of block totals + degree-bucket scan (fused)
__global__ void scan2_kernel(int nblocks, int n) {
    int t = threadIdx.x;  // 64 threads
    int v = (t < nblocks) ? g_bsum[t] : 0;
    int x = v;
    int lane = t & 31, wid = t >> 5;
    __shared__ int ws[2];
#pragma unroll
    for (int off = 1; off < 32; off <<= 1) {
        int y = __shfl_up_sync(0xffffffffu, x, off);
        if (lane >= off) x += y;
    }
    if (lane == 31) ws[wid] = x;
    __syncthreads();
    int add = (wid == 1) ? ws[0] : 0;
    g_boff[t] = add + x - v;
    if (t == 63) g_rowptr[n] = add + x;
    if (t == 0) {
        int run = 0;
        for (int i = 0; i < 64; i++) { g_dcur[i] = run; run += g_dhist[i]; }
    }
}

// phase 3: finalize rowptr/cursor + degree-bucket scatter -> perm (fused)
__global__ void scan3_kernel(int n) {
    int idx = blockIdx.x * blockDim.x + threadIdx.x;
    if (idx < n) {
        int r = g_rowptr[idx] + g_boff[idx >> 10];
        g_rowptr[idx] = r;
        g_cursor[idx] = r;
        int pos = atomicAdd(&g_dcur[min(g_deg[idx], 63)], 1);
        g_perm[pos] = idx;
    }
}

__global__ void scatter_kernel(const int* __restrict__ edges, int m) {
    int e = blockIdx.x * blockDim.x + threadIdx.x;
    if (e < m) {
        int d = edges[m + e];
        int pos = atomicAdd(&g_cursor[d], 1);
        g_colsrc[pos] = edges[e];
    }
}

// Sort each row's src list: deterministic accumulation order.
__global__ void sort_rows(int n) {
    int node = blockIdx.x * blockDim.x + threadIdx.x;
    if (node >= n) return;
    int s = g_rowptr[node], e = g_rowptr[node + 1];
    for (int i = s + 1; i < e; i++) {
        int v = g_colsrc[i];
        int j = i - 1;
        while (j >= s && g_colsrc[j] > v) { g_colsrc[j + 1] = g_colsrc[j]; j--; }
        g_colsrc[j + 1] = v;
    }
}

// ---------------------------------------------------------------------------
__device__ __forceinline__ void cvt12_ab(uint4 a, uint2 b, float* f) {
    float2 t;
    t = __half22float2(*(__half2*)&a.x); f[0] = t.x;  f[1] = t.y;
    t = __half22float2(*(__half2*)&a.y); f[2] = t.x;  f[3] = t.y;
    t = __half22float2(*(__half2*)&a.z); f[4] = t.x;  f[5] = t.y;
    t = __half22float2(*(__half2*)&a.w); f[6] = t.x;  f[7] = t.y;
    t = __half22float2(*(__half2*)&b.x); f[8] = t.x;  f[9] = t.y;
    t = __half22float2(*(__half2*)&b.y); f[10] = t.x; f[11] = t.y;
}

// load one smem entry: 16B chunk + 8B chunk (2 LDS, conflict-free)
__device__ __forceinline__ void ld_entry(const char* ebase, int lane, float* f) {
    uint4 a = *(const uint4*)(ebase + lane * 16);
    uint2 b = *(const uint2*)(ebase + 512 + lane * 8);
    cvt12_ab(a, b, f);
}

__device__ __forceinline__ float dot12(const float* f, const float* c) {
    float a0 = f[0]*c[0] + f[1]*c[1] + f[2]*c[2] + f[3]*c[3];
    float a1 = f[4]*c[4] + f[5]*c[5] + f[6]*c[6] + f[7]*c[7];
    float a2 = f[8]*c[8] + f[9]*c[9] + f[10]*c[10] + f[11]*c[11];
    return a0 + a1 + a2;
}

// Persistent work-stealing routing layer — single wave of 740 blocks at
// 5 blocks/SM (20 warps/SM for latency hiding). Entry layout
// [16B x 32 lanes][8B x 32 lanes] per edge; 2-edge unrolled inner loop
// (fits the 102-reg budget of 5 blocks/SM); 2-wide overflow streaming.
// mode 0: write z_next = l2norm(relu(c)); mode 1: write relu(c) to fout.
__global__ void __launch_bounds__(128, 5)
routing_layer(const __half* __restrict__ zh_in, const float* __restrict__ z32_in,
              __half* __restrict__ zh_out, float* __restrict__ z32_out,
              float* __restrict__ fout, int n, int mode, int widx) {
    extern __shared__ char sm[];
    __shared__ int chunk_s;
    int lane = threadIdx.x & 31;
    int warp = threadIdx.x >> 5;
    int group = lane >> 3;
    int cap = lane & 7;
    unsigned mask = 0xFFu << (group << 3);
    int local = warp * 4 + group;
    int nchunks = (n + 15) / 16;

    char* wslab = sm + warp * WSLAB;

    while (true) {
        if (threadIdx.x == 0) chunk_s = atomicAdd(&g_work[widx], 1);
        __syncthreads();
        int chunk = chunk_s;
        __syncthreads();   // chunk_s safe to overwrite next round
        if (chunk >= nchunks) break;

        int slot = chunk * 16 + local;
        bool valid = slot < n;
        int node = valid ? g_perm[(n - 1) - slot] : 0;   // descending degree

        int s = 0, deg = 0;
        if (valid) { s = g_rowptr[node]; deg = g_rowptr[node + 1] - s; }
        int cached = min(deg, CAP);

        // ---- fill: gather cached neighbor z rows, src index prefetched ----
        {
            int e = 0;
            int src = (e < cached) ? g_colsrc[s + e] : 0;
            for (; e < cached; e++) {
                int nsrc = (e + 1 < cached) ? g_colsrc[s + e + 1] : 0;
                const uint2* gz = (const uint2*)(zh_in + (size_t)src * D) + cap * 3;
                uint2 d0 = gz[0], d1 = gz[1], d2 = gz[2];
                char* ebase = wslab + e * 768;
                *(uint4*)(ebase + lane * 16) = make_uint4(d0.x, d0.y, d1.x, d1.y);
                *(uint2*)(ebase + 512 + lane * 8) = d2;
                src = nsrc;
            }
        }

        // ---- z_self (fp32); c init = z ----
        float z[12], c[12];
        if (valid) {
            const float4* zb = (const float4*)(z32_in + (size_t)node * D + cap * FAC);
            float4 a0 = zb[0], a1 = zb[1], a2 = zb[2];
            z[0] = a0.x; z[1] = a0.y; z[2]  = a0.z; z[3]  = a0.w;
            z[4] = a1.x; z[5] = a1.y; z[6]  = a1.z; z[7]  = a1.w;
            z[8] = a2.x; z[9] = a2.y; z[10] = a2.z; z[11] = a2.w;
#pragma unroll
            for (int i = 0; i < 12; i++) c[i] = z[i];
        }
        __syncwarp();

        // ---- 6 routing iterations from smem / registers ----
        for (int it = 0; it < 6; it++) {
            float acc[12];
#pragma unroll
            for (int i = 0; i < 12; i++) acc[i] = 0.f;

            int e = 0;
            // 2-edge unrolled: two independent chains in flight
            for (; e + 1 < cached; e += 2) {
                const char* p0 = wslab + e * 768;
                float f0[12], f1[12];
                ld_entry(p0,       lane, f0);
                ld_entry(p0 + 768, lane, f1);
                float ex0 = __expf(dot12(f0, c));
                float ex1 = __expf(dot12(f1, c));
                float s0 = gsum8(ex0, mask);
                float s1 = gsum8(ex1, mask);
                float p0_ = __fdividef(ex0, s0);
                float p1_ = __fdividef(ex1, s1);
#pragma unroll
                for (int i = 0; i < 12; i++) acc[i] += p0_ * f0[i] + p1_ * f1[i];
            }
            if (e < cached) {
                const char* p0 = wslab + e * 768;
                float f0[12];
                ld_entry(p0, lane, f0);
                float ex = __expf(dot12(f0, c));
                float sm_ = gsum8(ex, mask);
                float p = __fdividef(ex, sm_);
#pragma unroll
                for (int i = 0; i < 12; i++) acc[i] += p * f0[i];
            }
            // overflow edges streamed from L2, 2-wide (6 LDGs in flight)
            {
                int e2 = cached;
                for (; e2 + 1 < deg; e2 += 2) {
                    const uint2* ga = (const uint2*)(zh_in + (size_t)g_colsrc[s + e2] * D + cap * FAC);
                    const uint2* gb = (const uint2*)(zh_in + (size_t)g_colsrc[s + e2 + 1] * D + cap * FAC);
                    uint2 A0 = ga[0], A1 = ga[1], A2 = ga[2];
                    uint2 B0 = gb[0], B1 = gb[1], B2 = gb[2];
                    float fA[12], fB[12];
                    cvt12_ab(make_uint4(A0.x, A0.y, A1.x, A1.y), A2, fA);
                    cvt12_ab(make_uint4(B0.x, B0.y, B1.x, B1.y), B2, fB);
                    float exA = __expf(dot12(fA, c));
                    float exB = __expf(dot12(fB, c));
                    float sA = gsum8(exA, mask);
                    float sB = gsum8(exB, mask);
                    float pA = __fdividef(exA, sA);
                    float pB = __fdividef(exB, sB);
#pragma unroll
                    for (int i = 0; i < 12; i++) acc[i] += pA * fA[i] + pB * fB[i];
                }
                if (e2 < deg) {
                    const uint2* ga = (const uint2*)(zh_in + (size_t)g_colsrc[s + e2] * D + cap * FAC);
                    uint2 A0 = ga[0], A1 = ga[1], A2 = ga[2];
                    float fA[12];
                    cvt12_ab(make_uint4(A0.x, A0.y, A1.x, A1.y), A2, fA);
                    float ex = __expf(dot12(fA, c));
                    float sm_ = gsum8(ex, mask);
                    float p = __fdividef(ex, sm_);
#pragma unroll
                    for (int i = 0; i < 12; i++) acc[i] += p * fA[i];
                }
            }

            float v[12];
            float ss = 0.f;
#pragma unroll
            for (int i = 0; i < 12; i++) { v[i] = z[i] + acc[i]; ss += v[i] * v[i]; }
            float rn = rsqrtf(ss + 1e-12f);
#pragma unroll
            for (int i = 0; i < 12; i++) c[i] = v[i] * rn;
        }

        if (valid) {
#pragma unroll
            for (int i = 0; i < 12; i++) c[i] = fmaxf(c[i], 0.f);  // relu
            if (mode == 0) {
                float ss = 0.f;
#pragma unroll
                for (int i = 0; i < 12; i++) ss += c[i] * c[i];
                float rn = rsqrtf(ss + 1e-12f);
#pragma unroll
                for (int i = 0; i < 12; i++) c[i] *= rn;
                float4* zp = (float4*)(z32_out + (size_t)node * D + cap * FAC);
                zp[0] = make_float4(c[0], c[1], c[2], c[3]);
                zp[1] = make_float4(c[4], c[5], c[6], c[7]);
                zp[2] = make_float4(c[8], c[9], c[10], c[11]);
                uint2* zh = (uint2*)(zh_out + (size_t)node * D + cap * FAC);
                __half2 h0 = __floats2half2_rn(c[0], c[1]);
                __half2 h1 = __floats2half2_rn(c[2], c[3]);
                __half2 h2 = __floats2half2_rn(c[4], c[5]);
                __half2 h3 = __floats2half2_rn(c[6], c[7]);
                __half2 h4 = __floats2half2_rn(c[8], c[9]);
                __half2 h5 = __floats2half2_rn(c[10], c[11]);
                zh[0] = make_uint2(*(unsigned*)&h0, *(unsigned*)&h1);
                zh[1] = make_uint2(*(unsigned*)&h2, *(unsigned*)&h3);
                zh[2] = make_uint2(*(unsigned*)&h4, *(unsigned*)&h5);
            } else {
                float4* fo = (float4*)(fout + (size_t)node * D + cap * FAC);
                fo[0] = make_float4(c[0], c[1], c[2], c[3]);
                fo[1] = make_float4(c[4], c[5], c[6], c[7]);
                fo[2] = make_float4(c[8], c[9], c[10], c[11]);
            }
        }
    }
}

// ---------------------------------------------------------------------------
extern "C" void kernel_launch(void* const* d_in, const int* in_sizes, int n_in,
                              void* d_out, int out_size) {
    const float* X     = (const float*)d_in[0];
    const int*   edges = (const int*)d_in[1];
    const float* W     = (const float*)d_in[2];
    const float* b     = (const float*)d_in[3];
    int n = in_sizes[0] / 256;   // 50000
    int m = in_sizes[1] / 2;     // 800000

    cudaFuncSetAttribute(routing_layer,
                         cudaFuncAttributeMaxDynamicSharedMemorySize, ROUTE_SMEM);

    __half* zha; cudaGetSymbolAddress((void**)&zha, g_zh_a);
    __half* zhb; cudaGetSymbolAddress((void**)&zhb, g_zh_b);
    float* z32a; cudaGetSymbolAddress((void**)&z32a, g_z32_a);
    float* z32b; cudaGetSymbolAddress((void**)&z32b, g_z32_b);

    // zero + W transpose + work-counter reset, then init+prep fused
    zero_wt_kernel<<<(n + 255) / 256, 256>>>(W, n);
    init_gemm<<<(n + 31) / 32, 96>>>(X, b, n);

    // CSR by dst (deterministic: rows sorted by src); perm fused into scans
    hist_kernel<<<(m + 255) / 256, 256>>>(edges, m);
    int sblocks = (n + 1023) / 1024;   // 49 <= 64
    scan1_kernel<<<sblocks, 1024>>>(n);
    scan2_kernel<<<1, 64>>>(sblocks, n);
    scan3_kernel<<<(n + 255) / 256, 256>>>(n);
    scatter_kernel<<<(m + 255) / 256, 256>>>(edges, m);
    sort_rows<<<(n + 255) / 256, 256>>>(n);

    // 4 persistent routing layers (z double-buffered)
    routing_layer<<<ROUTE_GRID, 128, ROUTE_SMEM>>>(zha, z32a, zhb, z32b, nullptr, n, 0, 0);
    routing_layer<<<ROUTE_GRID, 128, ROUTE_SMEM>>>(zhb, z32b, zha, z32a, nullptr, n, 0, 1);
    routing_layer<<<ROUTE_GRID, 128, ROUTE_SMEM>>>(zha, z32a, zhb, z32b, nullptr, n, 0, 2);
    routing_layer<<<ROUTE_GRID, 128, ROUTE_SMEM>>>(zhb, z32b, nullptr, nullptr, (float*)d_out, n, 1, 3);
}

// round 13
// speedup vs baseline: 1.0892x; 1.0892x over previous
#include <cuda_runtime.h>
#include <cuda_fp16.h>

// Problem constants (fixed shapes)
#define N_MAX 50000
#define M_MAX 800000
#define D 96          // K*FAC
#define KCAP 8
#define FAC 12

#define CAP 18                        // cached neighbors per node in smem (fp16)
#define WSLAB (CAP * 768)             // per-warp slab: CAP entries x 768B
#define ROUTE_SMEM (4 * WSLAB)        // 55296 B per 128-thread block -> 4 blocks/SM
#define ROUTE_GRID 592                // 148 SMs x 4 resident blocks: exactly one wave

typedef unsigned long long u64;

// Static scratch (no allocations allowed)
__device__ __half g_zh_a[N_MAX * D];   // fp16 z double-buffer A (gather source)
__device__ __half g_zh_b[N_MAX * D];   // fp16 z double-buffer B
__device__ float  g_z32_a[N_MAX * D];  // fp32 z double-buffer A (self-term)
__device__ float  g_z32_b[N_MAX * D];  // fp32 z double-buffer B
__device__ float  g_wt[D * 256];       // W transposed to [out=96][in=256]
__device__ int    g_deg[N_MAX];
__device__ int    g_rowptr[N_MAX + 1];
__device__ int    g_cursor[N_MAX];
__device__ int    g_colsrc[M_MAX];
__device__ int    g_bsum[64];
__device__ int    g_boff[64];
__device__ int    g_dhist[64];
__device__ int    g_dcur[64];
__device__ int    g_perm[N_MAX];
__device__ int    g_work[4];           // per-layer work-stealing counters
__device__ int    g_bar[4];            // per-layer global barrier counters

// ---------------- packed f32x2 helpers (init GEMM only) --------------------
__device__ __forceinline__ u64 pk2(float lo, float hi) {
    u64 r; asm("mov.b64 %0,{%1,%2};" : "=l"(r) : "f"(lo), "f"(hi)); return r;
}
__device__ __forceinline__ float2 upk2(u64 v) {
    float2 f; asm("mov.b64 {%0,%1},%2;" : "=f"(f.x), "=f"(f.y) : "l"(v)); return f;
}
__device__ __forceinline__ u64 fma2_(u64 a, u64 b, u64 c) {
    u64 d; asm("fma.rn.f32x2 %0,%1,%2,%3;" : "=l"(d) : "l"(a), "l"(b), "l"(c)); return d;
}

// 8-lane group sum (3-shuffle butterfly; fp32 redux unsupported on sm_103)
__device__ __forceinline__ float gsum8(float v, unsigned mask) {
    v += __shfl_xor_sync(mask, v, 1);
    v += __shfl_xor_sync(mask, v, 2);
    v += __shfl_xor_sync(mask, v, 4);
    return v;
}

// ---------------------------------------------------------------------------
// zero + W transpose fused; also resets work/barrier counters each replay.
__global__ void zero_wt_kernel(const float* __restrict__ W, int n) {
    int i = blockIdx.x * blockDim.x + threadIdx.x;
    if (i < n) g_deg[i] = 0;
    if (i < 64) g_dhist[i] = 0;
    if (i < 4) { g_work[i] = 0; g_bar[i] = 0; }
    if (i < D * 256) {
        int o = i >> 8, c = i & 255;
        int k = o / FAC, oo = o % FAC;
        g_wt[i] = W[k * (256 * FAC) + c * FAC + oo];
    }
}

// ---------------------------------------------------------------------------
// Init layer fused with prep: Z = relu(X.Wt + b) staged in smem, then
// z = l2norm(Z) written to z32_a (fp32) + zh_a (fp16). f32x2 FMA mainloop.
__global__ void __launch_bounds__(96) init_gemm(const float* __restrict__ X,
                                                const float* __restrict__ bv, int n) {
    __shared__ float xs[32][256];
    __shared__ float os[32][96];
    int t = threadIdx.x;
    int nb = blockIdx.x * 32;
    for (int j = t; j < 32 * 256; j += 96) {
        int q = j >> 8;
        xs[q][j & 255] = (nb + q < n) ? X[nb * 256 + j] : 0.f;
    }
    __syncthreads();

    u64 acc[32];
#pragma unroll
    for (int q = 0; q < 32; q++) acc[q] = 0ull;

    const float4* wrow = (const float4*)(g_wt + t * 256);
#pragma unroll 2
    for (int i4 = 0; i4 < 64; i4++) {
        float4 w = wrow[i4];
        u64 w01 = pk2(w.x, w.y);
        u64 w23 = pk2(w.z, w.w);
#pragma unroll
        for (int q = 0; q < 32; q++) {
            float4 xv = *(const float4*)&xs[q][i4 * 4];
            acc[q] = fma2_(w01, pk2(xv.x, xv.y), acc[q]);
            acc[q] = fma2_(w23, pk2(xv.z, xv.w), acc[q]);
        }
    }
    float bb = bv[t];
#pragma unroll
    for (int q = 0; q < 32; q++) {
        float2 h = upk2(acc[q]);
        os[q][t] = fmaxf(h.x + h.y + bb, 0.f);   // relu(Z)
    }
    __syncthreads();

    // prep: per (node, capsule) l2norm -> z32_a + zh_a
    for (int idx = t; idx < 32 * KCAP; idx += 96) {
        int q = idx >> 3, cp = idx & 7;
        if (nb + q >= n) continue;
        const float* r = &os[q][cp * FAC];
        float v[12];
        float s = 0.f;
#pragma unroll
        for (int i = 0; i < 12; i++) { v[i] = r[i]; s += v[i] * v[i]; }
        float rn = rsqrtf(s + 1e-12f);
#pragma unroll
        for (int i = 0; i < 12; i++) v[i] *= rn;
        int gi = ((nb + q) * KCAP + cp) * FAC;
        float4* zp = (float4*)(g_z32_a + gi);
        zp[0] = make_float4(v[0], v[1], v[2], v[3]);
        zp[1] = make_float4(v[4], v[5], v[6], v[7]);
        zp[2] = make_float4(v[8], v[9], v[10], v[11]);
        uint2* zh = (uint2*)(g_zh_a + gi);
        __half2 h0 = __floats2half2_rn(v[0], v[1]);
        __half2 h1 = __floats2half2_rn(v[2], v[3]);
        __half2 h2 = __floats2half2_rn(v[4], v[5]);
        __half2 h3 = __floats2half2_rn(v[6], v[7]);
        __half2 h4 = __floats2half2_rn(v[8], v[9]);
        __half2 h5 = __floats2half2_rn(v[10], v[11]);
        zh[0] = make_uint2(*(unsigned*)&h0, *(unsigned*)&h1);
        zh[1] = make_uint2(*(unsigned*)&h2, *(unsigned*)&h3);
        zh[2] = make_uint2(*(unsigned*)&h4, *(unsigned*)&h5);
    }
}

// ---------------------------------------------------------------------------
// CSR build: hist -> 3-phase hierarchical scan (with perm stages fused)
__global__ void hist_kernel(const int* __restrict__ edges, int m) {
    int e = blockIdx.x * blockDim.x + threadIdx.x;
    if (e < m) atomicAdd(&g_deg[edges[m + e]], 1);
}

// phase 1: block-local exclusive scan of degrees + degree histogram (fused)
__global__ void scan1_kernel(int n) {
    __shared__ int wsum[32];
    __shared__ int h[64];
    int t = threadIdx.x, lane = t & 31, wid = t >> 5;
    if (t < 64) h[t] = 0;
    int idx = blockIdx.x * 1024 + t;
    int v = (idx < n) ? g_deg[idx] : 0;
    int x = v;
#pragma unroll
    for (int off = 1; off < 32; off <<= 1) {
        int y = __shfl_up_sync(0xffffffffu, x, off);
        if (lane >= off) x += y;
    }
    if (lane == 31) wsum[wid] = x;
    __syncthreads();
    if (wid == 0) {
        int w = wsum[lane];
#pragma unroll
        for (int off = 1; off < 32; off <<= 1) {
            int y = __shfl_up_sync(0xffffffffu, w, off);
            if (lane >= off) w += y;
        }
        wsum[lane] = w;
    }
    if (idx < n) atomicAdd(&h[min(v, 63)], 1);
    __syncthreads();
    int pre = (wid > 0) ? wsum[wid - 1] : 0;
    if (idx < n) g_rowptr[idx] = pre + x - v;   // block-local exclusive
    if (t == 1023) g_bsum[blockIdx.x] = pre + x;
    if (t < 64 && h[t]) atomicAdd(&g_dhist[t], h[t]);
}

// phase 2: scan of block totals + degree-bucket scan (fused)
__global__ void scan2_kernel(int nblocks, int n) {
    int t = threadIdx.x;  // 64 threads
    int v = (t < nblocks) ? g_bsum[t] : 0;
    int x = v;
    int lane = t & 31, wid = t >> 5;
    __shared__ int ws[2];
#pragma unroll
    for (int off = 1; off < 32; off <<= 1) {
        int y = __shfl_up_sync(0xffffffffu, x, off);
        if (lane >= off) x += y;
    }
    if (lane == 31) ws[wid] = x;
    __syncthreads();
    int add = (wid == 1) ? ws[0] : 0;
    g_boff[t] = add + x - v;
    if (t == 63) g_rowptr[n] = add + x;
    if (t == 0) {
        int run = 0;
        for (int i = 0; i < 64; i++) { g_dcur[i] = run; run += g_dhist[i]; }
    }
}

// phase 3: finalize rowptr/cursor + degree-bucket scatter -> perm (fused)
__global__ void scan3_kernel(int n) {
    int idx = blockIdx.x * blockDim.x + threadIdx.x;
    if (idx < n) {
        int r = g_rowptr[idx] + g_boff[idx >> 10];
        g_rowptr[idx] = r;
        g_cursor[idx] = r;
        int pos = atomicAdd(&g_dcur[min(g_deg[idx], 63)], 1);
        g_perm[pos] = idx;
    }
}

__global__ void scatter_kernel(const int* __restrict__ edges, int m) {
    int e = blockIdx.x * blockDim.x + threadIdx.x;
    if (e < m) {
        int d = edges[m + e];
        int pos = atomicAdd(&g_cursor[d], 1);
        g_colsrc[pos] = edges[e];
    }
}

// Sort each row's src list: deterministic accumulation order.
__global__ void sort_rows(int n) {
    int node = blockIdx.x * blockDim.x + threadIdx.x;
    if (node >= n) return;
    int s = g_rowptr[node], e = g_rowptr[node + 1];
    for (int i = s + 1; i < e; i++) {
        int v = g_colsrc[i];
        int j = i - 1;
        while (j >= s && g_colsrc[j] > v) { g_colsrc[j + 1] = g_colsrc[j]; j--; }
        g_colsrc[j + 1] = v;
    }
}

// ---------------------------------------------------------------------------
__device__ __forceinline__ void cvt12_ab(uint4 a, uint2 b, float* f) {
    float2 t;
    t = __half22float2(*(__half2*)&a.x); f[0] = t.x;  f[1] = t.y;
    t = __half22float2(*(__half2*)&a.y); f[2] = t.x;  f[3] = t.y;
    t = __half22float2(*(__half2*)&a.z); f[4] = t.x;  f[5] = t.y;
    t = __half22float2(*(__half2*)&a.w); f[6] = t.x;  f[7] = t.y;
    t = __half22float2(*(__half2*)&b.x); f[8] = t.x;  f[9] = t.y;
    t = __half22float2(*(__half2*)&b.y); f[10] = t.x; f[11] = t.y;
}

// load one smem entry: 16B chunk + 8B chunk (2 LDS, conflict-free)
__device__ __forceinline__ void ld_entry(const char* ebase, int lane, float* f) {
    uint4 a = *(const uint4*)(ebase + lane * 16);
    uint2 b = *(const uint2*)(ebase + 512 + lane * 8);
    cvt12_ab(a, b, f);
}

__device__ __forceinline__ float dot12(const float* f, const float* c) {
    float a0 = f[0]*c[0] + f[1]*c[1] + f[2]*c[2] + f[3]*c[3];
    float a1 = f[4]*c[4] + f[5]*c[5] + f[6]*c[6] + f[7]*c[7];
    float a2 = f[8]*c[8] + f[9]*c[9] + f[10]*c[10] + f[11]*c[11];
    return a0 + a1 + a2;
}

// Persistent ALL-LAYERS routing kernel. Exactly one wave (592 blocks,
// 4/SM); device-side global barrier between layers (arrive + spin, safe
// because all blocks are resident). Per-WARP work stealing in 4-node
// chunks (no block syncs in the work phase). CAP-18 smem cache, 4-edge
// unrolled inner loop, 16B+8B conflict-free entries, pipelined overflow.
// Layers 0-2: z_next = l2norm(relu(c)) -> other buffer. Layer 3: relu(c) -> fout.
__global__ void __launch_bounds__(128, 4)
routing_all(__half* __restrict__ zha, float* __restrict__ z32a,
            __half* __restrict__ zhb, float* __restrict__ z32b,
            float* __restrict__ fout, int n) {
    extern __shared__ char sm[];
    int lane = threadIdx.x & 31;
    int warp = threadIdx.x >> 5;
    int group = lane >> 3;
    int cap = lane & 7;
    unsigned mask = 0xFFu << (group << 3);
    int nchunks = (n + 3) / 4;

    char* wslab = sm + warp * WSLAB;

    for (int layer = 0; layer < 4; layer++) {
        const __half* zh_in  = (layer & 1) ? zhb : zha;
        const float* z32_in  = (layer & 1) ? z32b : z32a;
        __half* zh_out       = (layer & 1) ? zha : zhb;
        float* z32_out       = (layer & 1) ? z32a : z32b;
        int last = (layer == 3);

        while (true) {
            int chunk;
            if (lane == 0) chunk = atomicAdd(&g_work[layer], 1);
            chunk = __shfl_sync(0xffffffffu, chunk, 0);
            if (chunk >= nchunks) break;

            int slot = chunk * 4 + group;
            bool valid = slot < n;
            int node = valid ? g_perm[(n - 1) - slot] : 0;   // descending degree

            int s = 0, deg = 0;
            if (valid) { s = g_rowptr[node]; deg = g_rowptr[node + 1] - s; }
            int cached = min(deg, CAP);

            // ---- fill: gather cached neighbor z rows, src prefetched ----
            {
                int e = 0;
                int src = (e < cached) ? g_colsrc[s + e] : 0;
                for (; e < cached; e++) {
                    int nsrc = (e + 1 < cached) ? g_colsrc[s + e + 1] : 0;
                    const uint2* gz = (const uint2*)(zh_in + (size_t)src * D) + cap * 3;
                    uint2 d0 = gz[0], d1 = gz[1], d2 = gz[2];
                    char* ebase = wslab + e * 768;
                    *(uint4*)(ebase + lane * 16) = make_uint4(d0.x, d0.y, d1.x, d1.y);
                    *(uint2*)(ebase + 512 + lane * 8) = d2;
                    src = nsrc;
                }
            }

            // ---- z_self (fp32); c init = z ----
            float z[12], c[12];
            if (valid) {
                const float4* zb = (const float4*)(z32_in + (size_t)node * D + cap * FAC);
                float4 a0 = zb[0], a1 = zb[1], a2 = zb[2];
                z[0] = a0.x; z[1] = a0.y; z[2]  = a0.z; z[3]  = a0.w;
                z[4] = a1.x; z[5] = a1.y; z[6]  = a1.z; z[7]  = a1.w;
                z[8] = a2.x; z[9] = a2.y; z[10] = a2.z; z[11] = a2.w;
#pragma unroll
                for (int i = 0; i < 12; i++) c[i] = z[i];
            }
            __syncwarp();

            // ---- 6 routing iterations from smem / registers ----
            for (int it = 0; it < 6; it++) {
                float acc[12];
#pragma unroll
                for (int i = 0; i < 12; i++) acc[i] = 0.f;

                int e = 0;
                // 4-edge unrolled: four independent chains in flight
                for (; e + 3 < cached; e += 4) {
                    const char* p0 = wslab + e * 768;
                    float f0[12], f1[12], f2[12], f3[12];
                    ld_entry(p0,        lane, f0);
                    ld_entry(p0 + 768,  lane, f1);
                    ld_entry(p0 + 1536, lane, f2);
                    ld_entry(p0 + 2304, lane, f3);
                    float ex0 = __expf(dot12(f0, c));
                    float ex1 = __expf(dot12(f1, c));
                    float ex2 = __expf(dot12(f2, c));
                    float ex3 = __expf(dot12(f3, c));
                    float s0 = gsum8(ex0, mask);
                    float s1 = gsum8(ex1, mask);
                    float s2 = gsum8(ex2, mask);
                    float s3 = gsum8(ex3, mask);
                    float p0_ = __fdividef(ex0, s0);
                    float p1_ = __fdividef(ex1, s1);
                    float p2_ = __fdividef(ex2, s2);
                    float p3_ = __fdividef(ex3, s3);
#pragma unroll
                    for (int i = 0; i < 12; i++)
                        acc[i] += p0_ * f0[i] + p1_ * f1[i] + p2_ * f2[i] + p3_ * f3[i];
                }
                // 2-edge remainder
                for (; e + 1 < cached; e += 2) {
                    const char* p0 = wslab + e * 768;
                    float f0[12], f1[12];
                    ld_entry(p0,       lane, f0);
                    ld_entry(p0 + 768, lane, f1);
                    float ex0 = __expf(dot12(f0, c));
                    float ex1 = __expf(dot12(f1, c));
                    float s0 = gsum8(ex0, mask);
                    float s1 = gsum8(ex1, mask);
                    float p0_ = __fdividef(ex0, s0);
                    float p1_ = __fdividef(ex1, s1);
#pragma unroll
                    for (int i = 0; i < 12; i++) acc[i] += p0_ * f0[i] + p1_ * f1[i];
                }
                if (e < cached) {
                    const char* p0 = wslab + e * 768;
                    float f0[12];
                    ld_entry(p0, lane, f0);
                    float ex = __expf(dot12(f0, c));
                    float sm_ = gsum8(ex, mask);
                    float p = __fdividef(ex, sm_);
#pragma unroll
                    for (int i = 0; i < 12; i++) acc[i] += p * f0[i];
                }
                // overflow edges streamed from L2, software-pipelined
                {
                    int e2 = cached;
                    uint2 P0, P1, P2;
                    if (e2 < deg) {
                        const uint2* gz = (const uint2*)(zh_in + (size_t)g_colsrc[s + e2] * D + cap * FAC);
                        P0 = gz[0]; P1 = gz[1]; P2 = gz[2];
                    }
                    for (; e2 < deg; e2++) {
                        uint2 A0 = P0, A1 = P1, A2 = P2;
                        if (e2 + 1 < deg) {
                            const uint2* gz = (const uint2*)(zh_in + (size_t)g_colsrc[s + e2 + 1] * D + cap * FAC);
                            P0 = gz[0]; P1 = gz[1]; P2 = gz[2];
                        }
                        float fA[12];
                        cvt12_ab(make_uint4(A0.x, A0.y, A1.x, A1.y), A2, fA);
                        float ex = __expf(dot12(fA, c));
                        float sm_ = gsum8(ex, mask);
                        float p = __fdividef(ex, sm_);
#pragma unroll
                        for (int i = 0; i < 12; i++) acc[i] += p * fA[i];
                    }
                }

                float v[12];
                float ss = 0.f;
#pragma unroll
                for (int i = 0; i < 12; i++) { v[i] = z[i] + acc[i]; ss += v[i] * v[i]; }
                float rn = rsqrtf(ss + 1e-12f);
#pragma unroll
                for (int i = 0; i < 12; i++) c[i] = v[i] * rn;
            }

            if (valid) {
#pragma unroll
                for (int i = 0; i < 12; i++) c[i] = fmaxf(c[i], 0.f);  // relu
                if (!last) {
                    float ss = 0.f;
#pragma unroll
                    for (int i = 0; i < 12; i++) ss += c[i] * c[i];
                    float rn = rsqrtf(ss + 1e-12f);
#pragma unroll
                    for (int i = 0; i < 12; i++) c[i] *= rn;
                    float4* zp = (float4*)(z32_out + (size_t)node * D + cap * FAC);
                    zp[0] = make_float4(c[0], c[1], c[2], c[3]);
                    zp[1] = make_float4(c[4], c[5], c[6], c[7]);
                    zp[2] = make_float4(c[8], c[9], c[10], c[11]);
                    uint2* zh = (uint2*)(zh_out + (size_t)node * D + cap * FAC);
                    __half2 h0 = __floats2half2_rn(c[0], c[1]);
                    __half2 h1 = __floats2half2_rn(c[2], c[3]);
                    __half2 h2 = __floats2half2_rn(c[4], c[5]);
                    __half2 h3 = __floats2half2_rn(c[6], c[7]);
                    __half2 h4 = __floats2half2_rn(c[8], c[9]);
                    __half2 h5 = __floats2half2_rn(c[10], c[11]);
                    zh[0] = make_uint2(*(unsigned*)&h0, *(unsigned*)&h1);
                    zh[1] = make_uint2(*(unsigned*)&h2, *(unsigned*)&h3);
                    zh[2] = make_uint2(*(unsigned*)&h4, *(unsigned*)&h5);
                } else {
                    float4* fo = (float4*)(fout + (size_t)node * D + cap * FAC);
                    fo[0] = make_float4(c[0], c[1], c[2], c[3]);
                    fo[1] = make_float4(c[4], c[5], c[6], c[7]);
                    fo[2] = make_float4(c[8], c[9], c[10], c[11]);
                }
            }
        }

        if (layer < 3) {
            // global barrier: release writes, arrive, spin until all arrive
            __syncthreads();
            if (threadIdx.x == 0) {
                __threadfence();
                atomicAdd(&g_bar[layer], 1);
                while (((volatile int*)g_bar)[layer] < gridDim.x) { }
            }
            __syncthreads();
            __threadfence();
        }
    }
}

// ---------------------------------------------------------------------------
extern "C" void kernel_launch(void* const* d_in, const int* in_sizes, int n_in,
                              void* d_out, int out_size) {
    const float* X     = (const float*)d_in[0];
    const int*   edges = (const int*)d_in[1];
    const float* W     = (const float*)d_in[2];
    const float* b     = (const float*)d_in[3];
    int n = in_sizes[0] / 256;   // 50000
    int m = in_sizes[1] / 2;     // 800000

    cudaFuncSetAttribute(routing_all,
                         cudaFuncAttributeMaxDynamicSharedMemorySize, ROUTE_SMEM);

    __half* zha; cudaGetSymbolAddress((void**)&zha, g_zh_a);
    __half* zhb; cudaGetSymbolAddress((void**)&zhb, g_zh_b);
    float* z32a; cudaGetSymbolAddress((void**)&z32a, g_z32_a);
    float* z32b; cudaGetSymbolAddress((void**)&z32b, g_z32_b);

    // zero + W transpose + counter reset, then init+prep fused
    zero_wt_kernel<<<(n + 255) / 256, 256>>>(W, n);
    init_gemm<<<(n + 31) / 32, 96>>>(X, b, n);

    // CSR by dst (deterministic: rows sorted by src); perm fused into scans
    hist_kernel<<<(m + 255) / 256, 256>>>(edges, m);
    int sblocks = (n + 1023) / 1024;   // 49 <= 64
    scan1_kernel<<<sblocks, 1024>>>(n);
    scan2_kernel<<<1, 64>>>(sblocks, n);
    scan3_kernel<<<(n + 255) / 256, 256>>>(n);
    scatter_kernel<<<(m + 255) / 256, 256>>>(edges, m);
    sort_rows<<<(n + 255) / 256, 256>>>(n);

    // single persistent kernel: all 4 routing layers with device barriers
    routing_all<<<ROUTE_GRID, 128, ROUTE_SMEM>>>(zha, z32a, zhb, z32b,
                                                 (float*)d_out, n);
}